// round 1
// baseline (speedup 1.0000x reference)
#include <cuda_runtime.h>

// Problem constants
constexpr int Bb   = 6;
constexpr int T    = 1024;
constexpr int DIN  = 256;
constexpr int DOUT = 512;
constexpr int G    = 8;
constexpr int KSP  = DIN * G;   // 2048

// Scratch (static device globals — allowed; no runtime allocation)
__device__ float g_xn[Bb * T * DIN];        // layernormed X, 6 MB
__device__ float g_silu[T * DIN];           // silu(xn[3]), 1 MB
__device__ float g_basis[4ull * T * KSP];   // basis for b in {0,1,4,5}, 32 MB

// ---------------------------------------------------------------------------
// Kernel 1: LayerNorm over D_IN per (b,t) row; also writes silu for b==3.
// One block per row, 256 threads (one per input dim).
// ---------------------------------------------------------------------------
__global__ void ln_kernel(const float* __restrict__ X,
                          const float* __restrict__ w,
                          const float* __restrict__ bias)
{
    int row = blockIdx.x;            // b*T + t
    int i   = threadIdx.x;           // 0..255
    float x = X[(size_t)row * DIN + i];

    float s = x, s2 = x * x;
    #pragma unroll
    for (int off = 16; off; off >>= 1) {
        s  += __shfl_xor_sync(0xffffffffu, s,  off);
        s2 += __shfl_xor_sync(0xffffffffu, s2, off);
    }
    __shared__ float ws[8], ws2[8];
    __shared__ float smu, srv;
    int wid = i >> 5, lid = i & 31;
    if (lid == 0) { ws[wid] = s; ws2[wid] = s2; }
    __syncthreads();
    if (i == 0) {
        float ts = 0.f, ts2 = 0.f;
        #pragma unroll
        for (int k = 0; k < 8; k++) { ts += ws[k]; ts2 += ws2[k]; }
        float mu  = ts * (1.f / DIN);
        float var = ts2 * (1.f / DIN) - mu * mu;   // biased variance
        smu = mu;
        srv = rsqrtf(var + 1e-5f);
    }
    __syncthreads();

    float xn = (x - smu) * srv * w[i] + bias[i];
    g_xn[(size_t)row * DIN + i] = xn;

    int bb = row / T;
    if (bb == 3) {
        float sig = 1.f / (1.f + __expf(-xn));
        g_silu[(size_t)(row - 3 * T) * DIN + i] = xn * sig;
    }
}

// ---------------------------------------------------------------------------
// Kernel 2: RBF basis for batches 0 and 4 -> slots 0 and 2.
// ---------------------------------------------------------------------------
__global__ void rbf_kernel(const float* __restrict__ grid)
{
    int sidx = blockIdx.y;           // 0 or 1
    int slot = sidx * 2;             // 0, 2
    int bb   = sidx * 4;             // 0, 4
    int e = blockIdx.x * 256 + threadIdx.x;    // 0 .. T*DIN-1
    int t = e >> 8, i = e & 255;

    float x = g_xn[(size_t)(bb * T + t) * DIN + i];
    float gr[G];
    #pragma unroll
    for (int g = 0; g < G; g++) gr[g] = __ldg(&grid[g]);

    const float invd = 7.f / 3.f;                 // 1/DENOM
    const float c    = -1.4426950408889634f;      // -log2(e)
    float o[G];
    #pragma unroll
    for (int g = 0; g < G; g++) {
        float d = (x - gr[g]) * invd;
        o[g] = exp2f(d * d * c);                  // exp(-d^2)
    }
    float* dst = g_basis + (size_t)slot * T * KSP + (size_t)t * KSP + i * 8;
    *(float4*)(dst)     = make_float4(o[0], o[1], o[2], o[3]);
    *(float4*)(dst + 4) = make_float4(o[4], o[5], o[6], o[7]);
}

// ---------------------------------------------------------------------------
// Kernel 3: B-spline (order 3) basis for batches 1 and 5 -> slots 1 and 3.
// ---------------------------------------------------------------------------
__global__ void bs_kernel(const float* __restrict__ grid)
{
    int sidx = blockIdx.y;           // 0 or 1
    int slot = 1 + sidx * 2;         // 1, 3
    int bb   = 1 + sidx * 4;         // 1, 5
    int e = blockIdx.x * 256 + threadIdx.x;
    int t = e >> 8, i = e & 255;

    float x = g_xn[(size_t)(bb * T + t) * DIN + i];
    float g[12];
    #pragma unroll
    for (int j = 0; j < 12; j++) g[j] = __ldg(&grid[j]);

    float bsv[11];
    #pragma unroll
    for (int j = 0; j < 11; j++)
        bsv[j] = (x >= g[j] && x < g[j + 1]) ? 1.f : 0.f;

    #pragma unroll
    for (int k = 1; k <= 3; k++) {
        #pragma unroll
        for (int j = 0; j <= 10 - k; j++) {
            float a = (x - g[j])         * __fdividef(1.f, g[j + k]     - g[j]);
            float b = (g[j + k + 1] - x) * __fdividef(1.f, g[j + k + 1] - g[j + 1]);
            bsv[j] = a * bsv[j] + b * bsv[j + 1];
        }
    }
    float* dst = g_basis + (size_t)slot * T * KSP + (size_t)t * KSP + i * 8;
    *(float4*)(dst)     = make_float4(bsv[0], bsv[1], bsv[2], bsv[3]);
    *(float4*)(dst + 4) = make_float4(bsv[4], bsv[5], bsv[6], bsv[7]);
}

// ---------------------------------------------------------------------------
// Kernel 4: combined GEMM.  C[m,n] = sum_k A[m,k] * W[n,k]   (both K-major)
//   z = 0..3 : A = g_basis slot z [1024 x 2048], W = spline_weight [512 x 2048]
//   z = 4    : A = g_silu         [1024 x 256 ], W = base_weight   [512 x 256 ]
// 128x128 block tile, BK=16, 8x8 per thread, register-prefetch double buffer.
// ---------------------------------------------------------------------------
__global__ void __launch_bounds__(256, 2)
gemm_kernel(const float* __restrict__ spline_w,
            const float* __restrict__ base_w,
            float* __restrict__ out)
{
    __shared__ float As[16][132];
    __shared__ float Bs[16][132];

    int z = blockIdx.z;
    const float* A;
    const float* W;
    int K, bb;
    if (z < 4) {
        A = g_basis + (size_t)z * T * KSP;
        W = spline_w;
        K = KSP;
        bb = (z == 0) ? 0 : (z == 1) ? 1 : (z == 2) ? 4 : 5;
    } else {
        A = g_silu;
        W = base_w;
        K = DIN;
        bb = 3;
    }
    float* C = out + (size_t)bb * T * DOUT;

    int m0 = blockIdx.y * 128;
    int n0 = blockIdx.x * 128;
    int tid = threadIdx.x;
    int tx = tid & 15, ty = tid >> 4;

    int lrow = tid >> 2;            // 0..63
    int lcol = (tid & 3) << 2;      // 0,4,8,12
    const float* Ald = A + (size_t)(m0 + lrow) * K + lcol;
    const float* Wld = W + (size_t)(n0 + lrow) * K + lcol;

    float4 ra0 = *(const float4*)(Ald);
    float4 ra1 = *(const float4*)(Ald + (size_t)64 * K);
    float4 rb0 = *(const float4*)(Wld);
    float4 rb1 = *(const float4*)(Wld + (size_t)64 * K);

    float acc[8][8] = {};

    for (int k0 = 0; k0 < K; k0 += 16) {
        // store current tile to smem (transposed)
        As[lcol + 0][lrow]      = ra0.x; As[lcol + 1][lrow]      = ra0.y;
        As[lcol + 2][lrow]      = ra0.z; As[lcol + 3][lrow]      = ra0.w;
        As[lcol + 0][lrow + 64] = ra1.x; As[lcol + 1][lrow + 64] = ra1.y;
        As[lcol + 2][lrow + 64] = ra1.z; As[lcol + 3][lrow + 64] = ra1.w;
        Bs[lcol + 0][lrow]      = rb0.x; Bs[lcol + 1][lrow]      = rb0.y;
        Bs[lcol + 2][lrow]      = rb0.z; Bs[lcol + 3][lrow]      = rb0.w;
        Bs[lcol + 0][lrow + 64] = rb1.x; Bs[lcol + 1][lrow + 64] = rb1.y;
        Bs[lcol + 2][lrow + 64] = rb1.z; Bs[lcol + 3][lrow + 64] = rb1.w;
        __syncthreads();

        // prefetch next tile into registers
        if (k0 + 16 < K) {
            ra0 = *(const float4*)(Ald + k0 + 16);
            ra1 = *(const float4*)(Ald + (size_t)64 * K + k0 + 16);
            rb0 = *(const float4*)(Wld + k0 + 16);
            rb1 = *(const float4*)(Wld + (size_t)64 * K + k0 + 16);
        }

        #pragma unroll
        for (int k = 0; k < 16; k++) {
            float4 a0 = *(const float4*)&As[k][ty * 4];
            float4 a1 = *(const float4*)&As[k][ty * 4 + 64];
            float4 b0 = *(const float4*)&Bs[k][tx * 4];
            float4 b1 = *(const float4*)&Bs[k][tx * 4 + 64];
            float av[8] = {a0.x, a0.y, a0.z, a0.w, a1.x, a1.y, a1.z, a1.w};
            float bv[8] = {b0.x, b0.y, b0.z, b0.w, b1.x, b1.y, b1.z, b1.w};
            #pragma unroll
            for (int ii = 0; ii < 8; ii++)
                #pragma unroll
                for (int jj = 0; jj < 8; jj++)
                    acc[ii][jj] = fmaf(av[ii], bv[jj], acc[ii][jj]);
        }
        __syncthreads();
    }

    #pragma unroll
    for (int ii = 0; ii < 8; ii++) {
        int m = m0 + ((ii < 4) ? (ty * 4 + ii) : (64 + ty * 4 + ii - 4));
        float* crow = C + (size_t)m * DOUT + n0;
        *(float4*)(crow + tx * 4)      = make_float4(acc[ii][0], acc[ii][1], acc[ii][2], acc[ii][3]);
        *(float4*)(crow + tx * 4 + 64) = make_float4(acc[ii][4], acc[ii][5], acc[ii][6], acc[ii][7]);
    }
}

// ---------------------------------------------------------------------------
// Kernel 5: DoG wavelet batch (b = 2).
//   y[t,o] = sum_i -u * exp(-0.5 u^2) * BW[o,i],  u = (xn[t,i]-tr[o,i])/sc[o,i]
// Block tile: 32 t x 32 o, 256 threads, 4 outputs per thread, i in chunks of 32.
// ---------------------------------------------------------------------------
__global__ void dog_kernel(const float* __restrict__ base_w,
                           const float* __restrict__ scale,
                           const float* __restrict__ trans,
                           float* __restrict__ out)
{
    __shared__ float xn_[32][33];
    __shared__ float tr_[32][33];
    __shared__ float rs_[32][33];
    __shared__ float bw_[32][33];

    int o0 = blockIdx.x * 32;
    int t0 = blockIdx.y * 32;
    int tid = threadIdx.x;
    int tx = tid & 31, ty = tid >> 5;   // tx: o lane, ty: 0..7

    float acc[4] = {0.f, 0.f, 0.f, 0.f};
    const float C = -0.7213475204444817f;   // -0.5*log2(e)

    for (int ic = 0; ic < DIN; ic += 32) {
        #pragma unroll
        for (int p = 0; p < 4; p++) {
            int idx = tid + p * 256;
            int r = idx >> 5, c = idx & 31;
            xn_[r][c] = g_xn[(size_t)(2 * T + t0 + r) * DIN + ic + c];
            size_t oi = (size_t)(o0 + r) * DIN + ic + c;
            float s = scale[oi];
            rs_[r][c] = __fdividef(1.f, s);
            tr_[r][c] = trans[oi];
            bw_[r][c] = base_w[oi];
        }
        __syncthreads();

        #pragma unroll
        for (int i = 0; i < 32; i++) {
            float trv = tr_[tx][i], rsv = rs_[tx][i], bwv = bw_[tx][i];
            #pragma unroll
            for (int j = 0; j < 4; j++) {
                float x = xn_[ty * 4 + j][i];
                float u = (x - trv) * rsv;
                float e = exp2f(u * u * C);       // exp(-0.5 u^2)
                acc[j] = fmaf(-u * e, bwv, acc[j]);
            }
        }
        __syncthreads();
    }

    #pragma unroll
    for (int j = 0; j < 4; j++)
        out[(size_t)(2 * T + t0 + ty * 4 + j) * DOUT + o0 + tx] = acc[j];
}

// ---------------------------------------------------------------------------
extern "C" void kernel_launch(void* const* d_in, const int* in_sizes, int n_in,
                              void* d_out, int out_size)
{
    const float* X        = (const float*)d_in[0];
    const float* ln_w     = (const float*)d_in[1];
    const float* ln_b     = (const float*)d_in[2];
    const float* base_w   = (const float*)d_in[3];
    const float* spline_w = (const float*)d_in[4];
    const float* scale    = (const float*)d_in[5];
    const float* trans    = (const float*)d_in[6];
    const float* grid_rbf = (const float*)d_in[7];
    const float* grid_bs  = (const float*)d_in[8];
    float* out = (float*)d_out;

    ln_kernel<<<Bb * T, 256>>>(X, ln_w, ln_b);
    rbf_kernel<<<dim3(T * DIN / 256, 2), 256>>>(grid_rbf);
    bs_kernel<<<dim3(T * DIN / 256, 2), 256>>>(grid_bs);
    gemm_kernel<<<dim3(DOUT / 128, T / 128, 5), 256>>>(spline_w, base_w, out);
    dog_kernel<<<dim3(DOUT / 32, T / 32), 256>>>(base_w, scale, trans, out);
}

// round 3
// speedup vs baseline: 1.6632x; 1.6632x over previous
#include <cuda_runtime.h>
#include <cuda_bf16.h>
#include <cstdint>

// Problem constants
constexpr int Bb   = 6;
constexpr int T    = 1024;
constexpr int DIN  = 256;
constexpr int DOUT = 512;
constexpr int G    = 8;
constexpr int KSP  = DIN * G;   // 2048

// ---------------------------------------------------------------------------
// Device scratch
// ---------------------------------------------------------------------------
__device__ __align__(16) float          g_xn[Bb * T * DIN];
__device__ __align__(16) __nv_bfloat16  g_silu_hi[T * DIN];
__device__ __align__(16) __nv_bfloat16  g_silu_lo[T * DIN];
__device__ __align__(16) __nv_bfloat16  g_basis_hi[4ull * T * KSP];
__device__ __align__(16) __nv_bfloat16  g_basis_lo[4ull * T * KSP];
__device__ __align__(16) __nv_bfloat16  g_sw_hi[DOUT * KSP];
__device__ __align__(16) __nv_bfloat16  g_sw_lo[DOUT * KSP];
__device__ __align__(16) __nv_bfloat16  g_bw_hi[DOUT * DIN];
__device__ __align__(16) __nv_bfloat16  g_bw_lo[DOUT * DIN];

// ---------------------------------------------------------------------------
// Helpers
// ---------------------------------------------------------------------------
__device__ __forceinline__ void bsplit(float x, __nv_bfloat16& h, __nv_bfloat16& l)
{
    __nv_bfloat16 hb = __float2bfloat16(x);
    h = hb;
    l = __float2bfloat16(x - __bfloat162float(hb));
}

__device__ __forceinline__ uint32_t pack2(__nv_bfloat16 a, __nv_bfloat16 b)
{
    __nv_bfloat162 p = __halves2bfloat162(a, b);
    return *reinterpret_cast<uint32_t*>(&p);
}

__device__ __forceinline__ uint32_t smem_u32(const void* p)
{
    uint32_t a;
    asm("{ .reg .u64 t; cvta.to.shared.u64 t, %1; cvt.u32.u64 %0, t; }" : "=r"(a) : "l"(p));
    return a;
}

__device__ __forceinline__ void cpa(uint32_t d, const void* s)
{
    asm volatile("cp.async.cg.shared.global [%0], [%1], 16;" :: "r"(d), "l"(s));
}
#define CP_COMMIT() asm volatile("cp.async.commit_group;" ::: "memory")
#define CP_WAIT1()  asm volatile("cp.async.wait_group 1;"  ::: "memory")
#define CP_WAIT0()  asm volatile("cp.async.wait_group 0;"  ::: "memory")

#define LDSM_X4(R0,R1,R2,R3,ADDR) \
    asm volatile("ldmatrix.sync.aligned.m8n8.x4.shared.b16 {%0,%1,%2,%3}, [%4];" \
        : "=r"(R0), "=r"(R1), "=r"(R2), "=r"(R3) : "r"(ADDR))

__device__ __forceinline__ void mma16816(float* c, const uint32_t* a, const uint32_t* b)
{
    asm volatile(
        "mma.sync.aligned.m16n8k16.row.col.f32.bf16.bf16.f32 "
        "{%0,%1,%2,%3}, {%4,%5,%6,%7}, {%8,%9}, {%0,%1,%2,%3};"
        : "+f"(c[0]), "+f"(c[1]), "+f"(c[2]), "+f"(c[3])
        : "r"(a[0]), "r"(a[1]), "r"(a[2]), "r"(a[3]), "r"(b[0]), "r"(b[1]));
}

// ---------------------------------------------------------------------------
// Kernel 1: LayerNorm; also silu hi/lo for b==3.
// ---------------------------------------------------------------------------
__global__ void ln_kernel(const float* __restrict__ X,
                          const float* __restrict__ w,
                          const float* __restrict__ bias)
{
    int row = blockIdx.x;
    int i   = threadIdx.x;
    float x = X[(size_t)row * DIN + i];

    float s = x, s2 = x * x;
    #pragma unroll
    for (int off = 16; off; off >>= 1) {
        s  += __shfl_xor_sync(0xffffffffu, s,  off);
        s2 += __shfl_xor_sync(0xffffffffu, s2, off);
    }
    __shared__ float ws[8], ws2[8];
    __shared__ float smu, srv;
    int wid = i >> 5, lid = i & 31;
    if (lid == 0) { ws[wid] = s; ws2[wid] = s2; }
    __syncthreads();
    if (i == 0) {
        float ts = 0.f, ts2 = 0.f;
        #pragma unroll
        for (int k = 0; k < 8; k++) { ts += ws[k]; ts2 += ws2[k]; }
        float mu  = ts * (1.f / DIN);
        float var = ts2 * (1.f / DIN) - mu * mu;
        smu = mu;
        srv = rsqrtf(var + 1e-5f);
    }
    __syncthreads();

    float xn = (x - smu) * srv * w[i] + bias[i];
    g_xn[(size_t)row * DIN + i] = xn;

    int bb = row / T;
    if (bb == 3) {
        float sig = 1.f / (1.f + __expf(-xn));
        float v = xn * sig;
        __nv_bfloat16 h, l;
        bsplit(v, h, l);
        g_silu_hi[(size_t)(row - 3 * T) * DIN + i] = h;
        g_silu_lo[(size_t)(row - 3 * T) * DIN + i] = l;
    }
}

// ---------------------------------------------------------------------------
// Kernel 2: weight split
// ---------------------------------------------------------------------------
__global__ void wsplit_kernel(const float* __restrict__ spline_w,
                              const float* __restrict__ base_w)
{
    int idx = blockIdx.x * 256 + threadIdx.x;
    const int NSP = DOUT * KSP;
    if (idx < NSP) {
        __nv_bfloat16 h, l;
        bsplit(spline_w[idx], h, l);
        g_sw_hi[idx] = h; g_sw_lo[idx] = l;
    } else {
        int j = idx - NSP;
        __nv_bfloat16 h, l;
        bsplit(base_w[j], h, l);
        g_bw_hi[j] = h; g_bw_lo[j] = l;
    }
}

// ---------------------------------------------------------------------------
// Kernel 3: RBF basis (batches 0,4 -> slots 0,2)
// ---------------------------------------------------------------------------
__global__ void rbf_kernel(const float* __restrict__ grid)
{
    int sidx = blockIdx.y;
    int slot = sidx * 2;
    int bb   = sidx * 4;
    int e = blockIdx.x * 256 + threadIdx.x;
    int t = e >> 8, i = e & 255;

    float x = g_xn[(size_t)(bb * T + t) * DIN + i];
    const float invd = 7.f / 3.f;
    const float c    = -1.4426950408889634f;
    __nv_bfloat16 h[G], l[G];
    #pragma unroll
    for (int g = 0; g < G; g++) {
        float d = (x - __ldg(&grid[g])) * invd;
        bsplit(exp2f(d * d * c), h[g], l[g]);
    }
    size_t off = (size_t)slot * T * KSP + (size_t)t * KSP + i * 8;
    uint4 uh = make_uint4(pack2(h[0],h[1]), pack2(h[2],h[3]), pack2(h[4],h[5]), pack2(h[6],h[7]));
    uint4 ul = make_uint4(pack2(l[0],l[1]), pack2(l[2],l[3]), pack2(l[4],l[5]), pack2(l[6],l[7]));
    *reinterpret_cast<uint4*>(g_basis_hi + off) = uh;
    *reinterpret_cast<uint4*>(g_basis_lo + off) = ul;
}

// ---------------------------------------------------------------------------
// Kernel 4: B-spline basis (batches 1,5 -> slots 1,3)
// ---------------------------------------------------------------------------
__global__ void bs_kernel(const float* __restrict__ grid)
{
    int sidx = blockIdx.y;
    int slot = 1 + sidx * 2;
    int bb   = 1 + sidx * 4;
    int e = blockIdx.x * 256 + threadIdx.x;
    int t = e >> 8, i = e & 255;

    float x = g_xn[(size_t)(bb * T + t) * DIN + i];
    float g[12];
    #pragma unroll
    for (int j = 0; j < 12; j++) g[j] = __ldg(&grid[j]);

    float bsv[11];
    #pragma unroll
    for (int j = 0; j < 11; j++)
        bsv[j] = (x >= g[j] && x < g[j + 1]) ? 1.f : 0.f;

    #pragma unroll
    for (int k = 1; k <= 3; k++) {
        #pragma unroll
        for (int j = 0; j <= 10 - k; j++) {
            float a = (x - g[j])         * __fdividef(1.f, g[j + k]     - g[j]);
            float b = (g[j + k + 1] - x) * __fdividef(1.f, g[j + k + 1] - g[j + 1]);
            bsv[j] = a * bsv[j] + b * bsv[j + 1];
        }
    }
    __nv_bfloat16 h[8], l[8];
    #pragma unroll
    for (int j = 0; j < 8; j++) bsplit(bsv[j], h[j], l[j]);

    size_t off = (size_t)slot * T * KSP + (size_t)t * KSP + i * 8;
    uint4 uh = make_uint4(pack2(h[0],h[1]), pack2(h[2],h[3]), pack2(h[4],h[5]), pack2(h[6],h[7]));
    uint4 ul = make_uint4(pack2(l[0],l[1]), pack2(l[2],l[3]), pack2(l[4],l[5]), pack2(l[6],l[7]));
    *reinterpret_cast<uint4*>(g_basis_hi + off) = uh;
    *reinterpret_cast<uint4*>(g_basis_lo + off) = ul;
}

// ---------------------------------------------------------------------------
// Kernel 5: HMMA GEMM (mma.sync bf16, 3-term split), 64x128 tiles, BK=32.
//   bid 0..255  : spline batches (z = bid>>6, 64 tiles each, K=2048)
//   bid 256..319: base batch (K=256)
// smem: 2 stages x (Ah 4K | Al 4K | Wh 8K | Wl 8K) = 48 KB, XOR-swizzled 64B rows
// ---------------------------------------------------------------------------
constexpr int BM = 64, BN = 128, BK = 32;
constexpr int OFF_AH = 0, OFF_AL = 4096, OFF_WH = 8192, OFF_WL = 16384;
constexpr int STAGE  = 24576;

__device__ __forceinline__ uint32_t swz(uint32_t row, uint32_t slot)
{
    return row * 64u + (((slot ^ ((row >> 1) & 3u)) & 3u) << 4);
}

__global__ void __launch_bounds__(256, 2)
gemm_mma(float* __restrict__ out)
{
    __shared__ __align__(16) char smem[2 * STAGE];
    uint32_t sbase = smem_u32(smem);

    int tid = threadIdx.x;
    int bid = blockIdx.x;
    int z, tt;
    if (bid < 256) { z = bid >> 6; tt = bid & 63; }
    else           { z = 4;        tt = bid - 256; }
    int mt = tt >> 2, nt = tt & 3;
    int bb = (z == 0) ? 0 : (z == 1) ? 1 : (z == 2) ? 4 : (z == 3) ? 5 : 3;

    const __nv_bfloat16 *Ah, *Al, *Wh, *Wl;
    int K;
    if (z < 4) {
        Ah = g_basis_hi + (size_t)z * T * KSP;
        Al = g_basis_lo + (size_t)z * T * KSP;
        Wh = g_sw_hi; Wl = g_sw_lo; K = KSP;
    } else {
        Ah = g_silu_hi; Al = g_silu_lo;
        Wh = g_bw_hi;  Wl = g_bw_lo;  K = DIN;
    }
    int m0 = mt * BM, n0 = nt * BN;
    int nc = K / BK;

    // ---- loader setup: one 16B chunk per (tile,row,slot) assignment
    int lrow = tid >> 2, lslot = tid & 3;        // A rows 0..63 ; W rows lrow, lrow+64
    const __nv_bfloat16* gAh = Ah + (size_t)(m0 + lrow) * K + lslot * 8;
    const __nv_bfloat16* gAl = Al + (size_t)(m0 + lrow) * K + lslot * 8;
    const __nv_bfloat16* gW0h = Wh + (size_t)(n0 + lrow) * K + lslot * 8;
    const __nv_bfloat16* gW1h = Wh + (size_t)(n0 + lrow + 64) * K + lslot * 8;
    const __nv_bfloat16* gW0l = Wl + (size_t)(n0 + lrow) * K + lslot * 8;
    const __nv_bfloat16* gW1l = Wl + (size_t)(n0 + lrow + 64) * K + lslot * 8;
    uint32_t sA  = swz(lrow, lslot);
    uint32_t sW0 = swz(lrow, lslot);
    uint32_t sW1 = swz(lrow + 64, lslot);

    // ---- compute setup
    int lane = tid & 31, wid = tid >> 5;
    int wm = wid >> 2, wn = wid & 3;             // warp tile: 32 rows x 32 cols
    uint32_t lr  = lane & 15;                    // ldmatrix row within 16
    uint32_t lks = lane >> 4;                    // 0/1 -> +16B slot

    float acc[2][4][4];
    #pragma unroll
    for (int a = 0; a < 2; a++)
        #pragma unroll
        for (int b = 0; b < 4; b++)
            #pragma unroll
            for (int cc = 0; cc < 4; cc++) acc[a][b][cc] = 0.f;

    // prologue
    {
        uint32_t sb = sbase;
        cpa(sb + OFF_AH + sA,  gAh);
        cpa(sb + OFF_AL + sA,  gAl);
        cpa(sb + OFF_WH + sW0, gW0h);
        cpa(sb + OFF_WH + sW1, gW1h);
        cpa(sb + OFF_WL + sW0, gW0l);
        cpa(sb + OFF_WL + sW1, gW1l);
        CP_COMMIT();
    }

    for (int c = 0; c < nc; c++) {
        if (c + 1 < nc) {
            uint32_t sb = sbase + ((c + 1) & 1) * STAGE;
            int kc = (c + 1) * BK;
            cpa(sb + OFF_AH + sA,  gAh + kc);
            cpa(sb + OFF_AL + sA,  gAl + kc);
            cpa(sb + OFF_WH + sW0, gW0h + kc);
            cpa(sb + OFF_WH + sW1, gW1h + kc);
            cpa(sb + OFF_WL + sW0, gW0l + kc);
            cpa(sb + OFF_WL + sW1, gW1l + kc);
            CP_COMMIT();
            CP_WAIT1();
        } else {
            CP_WAIT0();
        }
        __syncthreads();

        uint32_t sb = sbase + (c & 1) * STAGE;
        #pragma unroll
        for (int ks = 0; ks < 2; ks++) {
            uint32_t slot = 2 * ks + lks;
            uint32_t aF[2][4], bH[4][2], bL[4][2];

            // A-hi fragments
            #pragma unroll
            for (int mi = 0; mi < 2; mi++) {
                uint32_t ad = sb + OFF_AH + swz(wm * 32 + mi * 16 + lr, slot);
                LDSM_X4(aF[mi][0], aF[mi][1], aF[mi][2], aF[mi][3], ad);
            }
            // W-hi fragments
            #pragma unroll
            for (int p = 0; p < 2; p++) {
                uint32_t t0, t1, t2, t3;
                uint32_t ad = sb + OFF_WH + swz(wn * 32 + p * 16 + lr, slot);
                LDSM_X4(t0, t1, t2, t3, ad);
                bH[2*p][0] = t0; bH[2*p][1] = t2;
                bH[2*p+1][0] = t1; bH[2*p+1][1] = t3;
            }
            // term 1: Ah * Wh
            #pragma unroll
            for (int mi = 0; mi < 2; mi++)
                #pragma unroll
                for (int ni = 0; ni < 4; ni++)
                    mma16816(acc[mi][ni], aF[mi], bH[ni]);

            // W-lo fragments
            #pragma unroll
            for (int p = 0; p < 2; p++) {
                uint32_t t0, t1, t2, t3;
                uint32_t ad = sb + OFF_WL + swz(wn * 32 + p * 16 + lr, slot);
                LDSM_X4(t0, t1, t2, t3, ad);
                bL[2*p][0] = t0; bL[2*p][1] = t2;
                bL[2*p+1][0] = t1; bL[2*p+1][1] = t3;
            }
            // term 2: Ah * Wl
            #pragma unroll
            for (int mi = 0; mi < 2; mi++)
                #pragma unroll
                for (int ni = 0; ni < 4; ni++)
                    mma16816(acc[mi][ni], aF[mi], bL[ni]);

            // A-lo fragments (reuse aF regs)
            #pragma unroll
            for (int mi = 0; mi < 2; mi++) {
                uint32_t ad = sb + OFF_AL + swz(wm * 32 + mi * 16 + lr, slot);
                LDSM_X4(aF[mi][0], aF[mi][1], aF[mi][2], aF[mi][3], ad);
            }
            // term 3: Al * Wh
            #pragma unroll
            for (int mi = 0; mi < 2; mi++)
                #pragma unroll
                for (int ni = 0; ni < 4; ni++)
                    mma16816(acc[mi][ni], aF[mi], bH[ni]);
        }
        __syncthreads();
    }

    // epilogue
    float* Cb = out + (size_t)bb * T * DOUT;
    int rbase = m0 + wm * 32 + (lane >> 2);
    int cbase = n0 + wn * 32 + (lane & 3) * 2;
    #pragma unroll
    for (int mi = 0; mi < 2; mi++) {
        #pragma unroll
        for (int ni = 0; ni < 4; ni++) {
            int r = rbase + mi * 16;
            int cc = cbase + ni * 8;
            *reinterpret_cast<float2*>(&Cb[(size_t)r * DOUT + cc]) =
                make_float2(acc[mi][ni][0], acc[mi][ni][1]);
            *reinterpret_cast<float2*>(&Cb[(size_t)(r + 8) * DOUT + cc]) =
                make_float2(acc[mi][ni][2], acc[mi][ni][3]);
        }
    }
}

// ---------------------------------------------------------------------------
// Kernel 6: DoG wavelet batch (b = 2)
// ---------------------------------------------------------------------------
__global__ void dog_kernel(const float* __restrict__ base_w,
                           const float* __restrict__ scale,
                           const float* __restrict__ trans,
                           float* __restrict__ out)
{
    __shared__ float xn_[32][33];
    __shared__ float tr_[32][33];
    __shared__ float rs_[32][33];
    __shared__ float bw_[32][33];

    int o0 = blockIdx.x * 32;
    int t0 = blockIdx.y * 32;
    int tid = threadIdx.x;
    int tx = tid & 31, ty = tid >> 5;

    float acc[4] = {0.f, 0.f, 0.f, 0.f};
    const float C = -0.7213475204444817f;

    for (int ic = 0; ic < DIN; ic += 32) {
        #pragma unroll
        for (int p = 0; p < 4; p++) {
            int idx = tid + p * 256;
            int r = idx >> 5, c = idx & 31;
            xn_[r][c] = g_xn[(size_t)(2 * T + t0 + r) * DIN + ic + c];
            size_t oi = (size_t)(o0 + r) * DIN + ic + c;
            rs_[r][c] = __fdividef(1.f, scale[oi]);
            tr_[r][c] = trans[oi];
            bw_[r][c] = base_w[oi];
        }
        __syncthreads();

        #pragma unroll
        for (int i = 0; i < 32; i++) {
            float trv = tr_[tx][i], rsv = rs_[tx][i], bwv = bw_[tx][i];
            #pragma unroll
            for (int j = 0; j < 4; j++) {
                float x = xn_[ty * 4 + j][i];
                float u = (x - trv) * rsv;
                float e = exp2f(u * u * C);
                acc[j] = fmaf(-u * e, bwv, acc[j]);
            }
        }
        __syncthreads();
    }

    #pragma unroll
    for (int j = 0; j < 4; j++)
        out[(size_t)(2 * T + t0 + ty * 4 + j) * DOUT + o0 + tx] = acc[j];
}

// ---------------------------------------------------------------------------
extern "C" void kernel_launch(void* const* d_in, const int* in_sizes, int n_in,
                              void* d_out, int out_size)
{
    const float* X        = (const float*)d_in[0];
    const float* ln_w     = (const float*)d_in[1];
    const float* ln_b     = (const float*)d_in[2];
    const float* base_w   = (const float*)d_in[3];
    const float* spline_w = (const float*)d_in[4];
    const float* scale    = (const float*)d_in[5];
    const float* trans    = (const float*)d_in[6];
    const float* grid_rbf = (const float*)d_in[7];
    const float* grid_bs  = (const float*)d_in[8];
    float* out = (float*)d_out;

    wsplit_kernel<<<(DOUT * KSP + DOUT * DIN) / 256, 256>>>(spline_w, base_w);
    ln_kernel<<<Bb * T, 256>>>(X, ln_w, ln_b);
    rbf_kernel<<<dim3(T * DIN / 256, 2), 256>>>(grid_rbf);
    bs_kernel<<<dim3(T * DIN / 256, 2), 256>>>(grid_bs);
    gemm_mma<<<320, 256>>>(out);
    dog_kernel<<<dim3(DOUT / 32, T / 32), 256>>>(base_w, scale, trans, out);
}

// round 4
// speedup vs baseline: 1.8225x; 1.0958x over previous
#include <cuda_runtime.h>
#include <cuda_bf16.h>
#include <cstdint>

// Problem constants
constexpr int Bb   = 6;
constexpr int T    = 1024;
constexpr int DIN  = 256;
constexpr int DOUT = 512;
constexpr int G    = 8;
constexpr int KSP  = DIN * G;   // 2048

// ---------------------------------------------------------------------------
// Device scratch
// ---------------------------------------------------------------------------
__device__ __align__(16) float          g_xn2[T * DIN];           // LN'd batch 2 (dog)
__device__ __align__(16) __nv_bfloat16  g_silu_hi[T * DIN];
__device__ __align__(16) __nv_bfloat16  g_silu_lo[T * DIN];
__device__ __align__(16) __nv_bfloat16  g_basis_hi[4ull * T * KSP];
__device__ __align__(16) __nv_bfloat16  g_basis_lo[4ull * T * KSP];
__device__ __align__(16) __nv_bfloat16  g_sw_hi[DOUT * KSP];
__device__ __align__(16) __nv_bfloat16  g_sw_lo[DOUT * KSP];
__device__ __align__(16) __nv_bfloat16  g_bw_hi[DOUT * DIN];
__device__ __align__(16) __nv_bfloat16  g_bw_lo[DOUT * DIN];

// ---------------------------------------------------------------------------
// Helpers
// ---------------------------------------------------------------------------
__device__ __forceinline__ void bsplit(float x, __nv_bfloat16& h, __nv_bfloat16& l)
{
    __nv_bfloat16 hb = __float2bfloat16(x);
    h = hb;
    l = __float2bfloat16(x - __bfloat162float(hb));
}

__device__ __forceinline__ uint32_t pack2(__nv_bfloat16 a, __nv_bfloat16 b)
{
    __nv_bfloat162 p = __halves2bfloat162(a, b);
    return *reinterpret_cast<uint32_t*>(&p);
}

__device__ __forceinline__ uint32_t smem_u32(const void* p)
{
    uint32_t a;
    asm("{ .reg .u64 t; cvta.to.shared.u64 t, %1; cvt.u32.u64 %0, t; }" : "=r"(a) : "l"(p));
    return a;
}

__device__ __forceinline__ void cpa(uint32_t d, const void* s)
{
    asm volatile("cp.async.cg.shared.global [%0], [%1], 16;" :: "r"(d), "l"(s));
}
#define CP_COMMIT() asm volatile("cp.async.commit_group;" ::: "memory")
#define CP_WAIT1()  asm volatile("cp.async.wait_group 1;"  ::: "memory")
#define CP_WAIT0()  asm volatile("cp.async.wait_group 0;"  ::: "memory")

#define LDSM_X4(R0,R1,R2,R3,ADDR) \
    asm volatile("ldmatrix.sync.aligned.m8n8.x4.shared.b16 {%0,%1,%2,%3}, [%4];" \
        : "=r"(R0), "=r"(R1), "=r"(R2), "=r"(R3) : "r"(ADDR))

__device__ __forceinline__ void mma16816(float* c, const uint32_t* a, const uint32_t* b)
{
    asm volatile(
        "mma.sync.aligned.m16n8k16.row.col.f32.bf16.bf16.f32 "
        "{%0,%1,%2,%3}, {%4,%5,%6,%7}, {%8,%9}, {%0,%1,%2,%3};"
        : "+f"(c[0]), "+f"(c[1]), "+f"(c[2]), "+f"(c[3])
        : "r"(a[0]), "r"(a[1]), "r"(a[2]), "r"(a[3]), "r"(b[0]), "r"(b[1]));
}

// ---------------------------------------------------------------------------
// Kernel 1: fused prep.
//   bid < 6144           : one (b,t) row — LayerNorm then per-batch transform
//   bid in [6144, 10752) : weight split (spline_w, base_w -> bf16 hi/lo)
// ---------------------------------------------------------------------------
constexpr int LN_BLOCKS = Bb * T;                                   // 6144
constexpr int WS_ELEMS  = DOUT * KSP + DOUT * DIN;                  // 1179648
constexpr int WS_BLOCKS = WS_ELEMS / 256;                           // 4608

__global__ void prep_kernel(const float* __restrict__ X,
                            const float* __restrict__ w,
                            const float* __restrict__ bias,
                            const float* __restrict__ spline_w,
                            const float* __restrict__ base_w,
                            const float* __restrict__ grid_rbf,
                            const float* __restrict__ grid_bs)
{
    int bid = blockIdx.x;
    int tid = threadIdx.x;

    if (bid >= LN_BLOCKS) {
        // ---- weight split ----
        int idx = (bid - LN_BLOCKS) * 256 + tid;
        const int NSP = DOUT * KSP;
        __nv_bfloat16 h, l;
        if (idx < NSP) {
            bsplit(spline_w[idx], h, l);
            g_sw_hi[idx] = h; g_sw_lo[idx] = l;
        } else {
            int j = idx - NSP;
            bsplit(base_w[j], h, l);
            g_bw_hi[j] = h; g_bw_lo[j] = l;
        }
        return;
    }

    // ---- LayerNorm ----
    int row = bid;
    int bb  = row >> 10;          // T = 1024
    int t   = row & 1023;
    int i   = tid;
    float x = X[(size_t)row * DIN + i];

    float s = x, s2 = x * x;
    #pragma unroll
    for (int off = 16; off; off >>= 1) {
        s  += __shfl_xor_sync(0xffffffffu, s,  off);
        s2 += __shfl_xor_sync(0xffffffffu, s2, off);
    }
    __shared__ float ws[8], ws2[8];
    __shared__ float smu, srv;
    int wid = i >> 5, lid = i & 31;
    if (lid == 0) { ws[wid] = s; ws2[wid] = s2; }
    __syncthreads();
    if (i == 0) {
        float ts = 0.f, ts2 = 0.f;
        #pragma unroll
        for (int k = 0; k < 8; k++) { ts += ws[k]; ts2 += ws2[k]; }
        float mu  = ts * (1.f / DIN);
        float var = ts2 * (1.f / DIN) - mu * mu;
        smu = mu;
        srv = rsqrtf(var + 1e-5f);
    }
    __syncthreads();

    float xn = (x - smu) * srv * w[i] + bias[i];

    if (bb == 2) {                          // dog input
        g_xn2[(size_t)t * DIN + i] = xn;
        return;
    }
    if (bb == 3) {                          // silu
        float sig = 1.f / (1.f + __expf(-xn));
        float v = xn * sig;
        __nv_bfloat16 h, l;
        bsplit(v, h, l);
        g_silu_hi[(size_t)t * DIN + i] = h;
        g_silu_lo[(size_t)t * DIN + i] = l;
        return;
    }

    // spline batches -> basis slot
    int slot = (bb == 0) ? 0 : (bb == 1) ? 1 : (bb == 4) ? 2 : 3;
    __nv_bfloat16 h[G], l[G];

    if (bb == 0 || bb == 4) {
        // ---- RBF ----
        const float invd = 7.f / 3.f;
        const float c    = -1.4426950408889634f;
        #pragma unroll
        for (int g = 0; g < G; g++) {
            float d = (xn - __ldg(&grid_rbf[g])) * invd;
            bsplit(exp2f(d * d * c), h[g], l[g]);
        }
    } else {
        // ---- B-spline (uniform knots: constant reciprocals per level) ----
        float g[12];
        #pragma unroll
        for (int j = 0; j < 12; j++) g[j] = __ldg(&grid_bs[j]);
        float r1 = __fdividef(1.f, g[1] - g[0]);
        float r2 = __fdividef(1.f, g[2] - g[0]);
        float r3 = __fdividef(1.f, g[3] - g[0]);

        float bsv[11];
        #pragma unroll
        for (int j = 0; j < 11; j++)
            bsv[j] = (xn >= g[j] && xn < g[j + 1]) ? 1.f : 0.f;

        #pragma unroll
        for (int j = 0; j <= 9; j++)
            bsv[j] = (xn - g[j]) * r1 * bsv[j] + (g[j + 2] - xn) * r1 * bsv[j + 1];
        #pragma unroll
        for (int j = 0; j <= 8; j++)
            bsv[j] = (xn - g[j]) * r2 * bsv[j] + (g[j + 3] - xn) * r2 * bsv[j + 1];
        #pragma unroll
        for (int j = 0; j <= 7; j++)
            bsv[j] = (xn - g[j]) * r3 * bsv[j] + (g[j + 4] - xn) * r3 * bsv[j + 1];

        #pragma unroll
        for (int j = 0; j < 8; j++) bsplit(bsv[j], h[j], l[j]);
    }

    size_t off = (size_t)slot * T * KSP + (size_t)t * KSP + i * 8;
    uint4 uh = make_uint4(pack2(h[0],h[1]), pack2(h[2],h[3]), pack2(h[4],h[5]), pack2(h[6],h[7]));
    uint4 ul = make_uint4(pack2(l[0],l[1]), pack2(l[2],l[3]), pack2(l[4],l[5]), pack2(l[6],l[7]));
    *reinterpret_cast<uint4*>(g_basis_hi + off) = uh;
    *reinterpret_cast<uint4*>(g_basis_lo + off) = ul;
}

// ---------------------------------------------------------------------------
// Fat kernel: gemm tiles + dog tiles interleaved 5:8 over a period of 13 bids
// so each SM co-hosts tensor-bound and MUFU/FMA-bound CTAs.
// ---------------------------------------------------------------------------
constexpr int BM = 64, BN = 128, BK = 32;
constexpr int OFF_AH = 0, OFF_AL = 4096, OFF_WH = 8192, OFF_WL = 16384;
constexpr int STAGE  = 24576;
constexpr int SMEM_BYTES = 2 * STAGE;        // 48 KB (also covers dog's 16.9 KB)

constexpr int GEMM_TILES = 320;   // 256 spline + 64 base
constexpr int DOG_TILES  = 512;   // 16 o-tiles x 32 t-tiles
constexpr int FAT_BLOCKS = GEMM_TILES + DOG_TILES;   // 832 = 13 * 64

__device__ __forceinline__ uint32_t swz(uint32_t row, uint32_t slot)
{
    return row * 64u + (((slot ^ ((row >> 1) & 3u)) & 3u) << 4);
}

__device__ __forceinline__ void gemm_path(int gidx, char* smem, float* __restrict__ out)
{
    uint32_t sbase = smem_u32(smem);
    int tid = threadIdx.x;

    int z, tt;
    if (gidx < 256) { z = gidx >> 6; tt = gidx & 63; }
    else            { z = 4;         tt = gidx - 256; }
    int mt = tt >> 2, nt = tt & 3;
    int bb = (z == 0) ? 0 : (z == 1) ? 1 : (z == 2) ? 4 : (z == 3) ? 5 : 3;

    const __nv_bfloat16 *Ah, *Al, *Wh, *Wl;
    int K;
    if (z < 4) {
        Ah = g_basis_hi + (size_t)z * T * KSP;
        Al = g_basis_lo + (size_t)z * T * KSP;
        Wh = g_sw_hi; Wl = g_sw_lo; K = KSP;
    } else {
        Ah = g_silu_hi; Al = g_silu_lo;
        Wh = g_bw_hi;  Wl = g_bw_lo;  K = DIN;
    }
    int m0 = mt * BM, n0 = nt * BN;
    int nc = K / BK;

    int lrow = tid >> 2, lslot = tid & 3;
    const __nv_bfloat16* gAh  = Ah + (size_t)(m0 + lrow) * K + lslot * 8;
    const __nv_bfloat16* gAl  = Al + (size_t)(m0 + lrow) * K + lslot * 8;
    const __nv_bfloat16* gW0h = Wh + (size_t)(n0 + lrow) * K + lslot * 8;
    const __nv_bfloat16* gW1h = Wh + (size_t)(n0 + lrow + 64) * K + lslot * 8;
    const __nv_bfloat16* gW0l = Wl + (size_t)(n0 + lrow) * K + lslot * 8;
    const __nv_bfloat16* gW1l = Wl + (size_t)(n0 + lrow + 64) * K + lslot * 8;
    uint32_t sA  = swz(lrow, lslot);
    uint32_t sW0 = swz(lrow, lslot);
    uint32_t sW1 = swz(lrow + 64, lslot);

    int lane = tid & 31, wid = tid >> 5;
    int wm = wid >> 2, wn = wid & 3;
    uint32_t lr  = lane & 15;
    uint32_t lks = lane >> 4;

    float acc[2][4][4];
    #pragma unroll
    for (int a = 0; a < 2; a++)
        #pragma unroll
        for (int b = 0; b < 4; b++)
            #pragma unroll
            for (int cc = 0; cc < 4; cc++) acc[a][b][cc] = 0.f;

    {
        uint32_t sb = sbase;
        cpa(sb + OFF_AH + sA,  gAh);
        cpa(sb + OFF_AL + sA,  gAl);
        cpa(sb + OFF_WH + sW0, gW0h);
        cpa(sb + OFF_WH + sW1, gW1h);
        cpa(sb + OFF_WL + sW0, gW0l);
        cpa(sb + OFF_WL + sW1, gW1l);
        CP_COMMIT();
    }

    for (int c = 0; c < nc; c++) {
        if (c + 1 < nc) {
            uint32_t sb = sbase + ((c + 1) & 1) * STAGE;
            int kc = (c + 1) * BK;
            cpa(sb + OFF_AH + sA,  gAh + kc);
            cpa(sb + OFF_AL + sA,  gAl + kc);
            cpa(sb + OFF_WH + sW0, gW0h + kc);
            cpa(sb + OFF_WH + sW1, gW1h + kc);
            cpa(sb + OFF_WL + sW0, gW0l + kc);
            cpa(sb + OFF_WL + sW1, gW1l + kc);
            CP_COMMIT();
            CP_WAIT1();
        } else {
            CP_WAIT0();
        }
        __syncthreads();

        uint32_t sb = sbase + (c & 1) * STAGE;
        #pragma unroll
        for (int ks = 0; ks < 2; ks++) {
            uint32_t slot = 2 * ks + lks;
            uint32_t aF[2][4], bH[4][2], bL[4][2];

            #pragma unroll
            for (int mi = 0; mi < 2; mi++) {
                uint32_t ad = sb + OFF_AH + swz(wm * 32 + mi * 16 + lr, slot);
                LDSM_X4(aF[mi][0], aF[mi][1], aF[mi][2], aF[mi][3], ad);
            }
            #pragma unroll
            for (int p = 0; p < 2; p++) {
                uint32_t t0, t1, t2, t3;
                uint32_t ad = sb + OFF_WH + swz(wn * 32 + p * 16 + lr, slot);
                LDSM_X4(t0, t1, t2, t3, ad);
                bH[2*p][0] = t0; bH[2*p][1] = t2;
                bH[2*p+1][0] = t1; bH[2*p+1][1] = t3;
            }
            #pragma unroll
            for (int mi = 0; mi < 2; mi++)
                #pragma unroll
                for (int ni = 0; ni < 4; ni++)
                    mma16816(acc[mi][ni], aF[mi], bH[ni]);

            #pragma unroll
            for (int p = 0; p < 2; p++) {
                uint32_t t0, t1, t2, t3;
                uint32_t ad = sb + OFF_WL + swz(wn * 32 + p * 16 + lr, slot);
                LDSM_X4(t0, t1, t2, t3, ad);
                bL[2*p][0] = t0; bL[2*p][1] = t2;
                bL[2*p+1][0] = t1; bL[2*p+1][1] = t3;
            }
            #pragma unroll
            for (int mi = 0; mi < 2; mi++)
                #pragma unroll
                for (int ni = 0; ni < 4; ni++)
                    mma16816(acc[mi][ni], aF[mi], bL[ni]);

            #pragma unroll
            for (int mi = 0; mi < 2; mi++) {
                uint32_t ad = sb + OFF_AL + swz(wm * 32 + mi * 16 + lr, slot);
                LDSM_X4(aF[mi][0], aF[mi][1], aF[mi][2], aF[mi][3], ad);
            }
            #pragma unroll
            for (int mi = 0; mi < 2; mi++)
                #pragma unroll
                for (int ni = 0; ni < 4; ni++)
                    mma16816(acc[mi][ni], aF[mi], bH[ni]);
        }
        __syncthreads();
    }

    float* Cb = out + (size_t)bb * T * DOUT;
    int rbase = m0 + wm * 32 + (lane >> 2);
    int cbase = n0 + wn * 32 + (lane & 3) * 2;
    #pragma unroll
    for (int mi = 0; mi < 2; mi++) {
        #pragma unroll
        for (int ni = 0; ni < 4; ni++) {
            int r = rbase + mi * 16;
            int cc = cbase + ni * 8;
            *reinterpret_cast<float2*>(&Cb[(size_t)r * DOUT + cc]) =
                make_float2(acc[mi][ni][0], acc[mi][ni][1]);
            *reinterpret_cast<float2*>(&Cb[(size_t)(r + 8) * DOUT + cc]) =
                make_float2(acc[mi][ni][2], acc[mi][ni][3]);
        }
    }
}

struct DogS {
    float xn[32][33];
    float rs[32][33];
    float trrs[32][33];
    float nbw[32][33];
};

__device__ __forceinline__ void dog_path(int didx, char* smem,
                                         const float* __restrict__ base_w,
                                         const float* __restrict__ scale,
                                         const float* __restrict__ trans,
                                         float* __restrict__ out)
{
    DogS& S = *reinterpret_cast<DogS*>(smem);
    int o0 = (didx & 15) * 32;
    int t0 = (didx >> 4) * 32;
    int tid = threadIdx.x;
    int tx = tid & 31, ty = tid >> 5;

    float acc[4] = {0.f, 0.f, 0.f, 0.f};
    const float C = -0.7213475204444817f;   // -0.5*log2(e)

    for (int ic = 0; ic < DIN; ic += 32) {
        #pragma unroll
        for (int p = 0; p < 4; p++) {
            int idx = tid + p * 256;
            int r = idx >> 5, c = idx & 31;
            S.xn[r][c] = g_xn2[(size_t)(t0 + r) * DIN + ic + c];
            size_t oi = (size_t)(o0 + r) * DIN + ic + c;
            float rs = __fdividef(1.f, scale[oi]);
            S.rs[r][c]   = rs;
            S.trrs[r][c] = trans[oi] * rs;
            S.nbw[r][c]  = -base_w[oi];
        }
        __syncthreads();

        #pragma unroll
        for (int i = 0; i < 32; i++) {
            float trrs = S.trrs[tx][i], rsv = S.rs[tx][i], nbw = S.nbw[tx][i];
            #pragma unroll
            for (int j = 0; j < 4; j++) {
                float x = S.xn[ty * 4 + j][i];
                float u = fmaf(x, rsv, -trrs);
                float e = exp2f((u * C) * u);
                acc[j] = fmaf(u * e, nbw, acc[j]);
            }
        }
        __syncthreads();
    }

    #pragma unroll
    for (int j = 0; j < 4; j++)
        out[(size_t)(2 * T + t0 + ty * 4 + j) * DOUT + o0 + tx] = acc[j];
}

__global__ void __launch_bounds__(256, 2)
fat_kernel(float* __restrict__ out,
           const float* __restrict__ base_w,
           const float* __restrict__ scale,
           const float* __restrict__ trans)
{
    __shared__ __align__(16) char smem[SMEM_BYTES];
    int bid = blockIdx.x;
    int grp = bid / 13, rem = bid % 13;    // 832 = 13 * 64; 5 gemm + 8 dog per group
    if (rem < 5) gemm_path(grp * 5 + rem, smem, out);
    else         dog_path(grp * 8 + (rem - 5), smem, base_w, scale, trans, out);
}

// ---------------------------------------------------------------------------
extern "C" void kernel_launch(void* const* d_in, const int* in_sizes, int n_in,
                              void* d_out, int out_size)
{
    const float* X        = (const float*)d_in[0];
    const float* ln_w     = (const float*)d_in[1];
    const float* ln_b     = (const float*)d_in[2];
    const float* base_w   = (const float*)d_in[3];
    const float* spline_w = (const float*)d_in[4];
    const float* scale    = (const float*)d_in[5];
    const float* trans    = (const float*)d_in[6];
    const float* grid_rbf = (const float*)d_in[7];
    const float* grid_bs  = (const float*)d_in[8];
    float* out = (float*)d_out;

    prep_kernel<<<LN_BLOCKS + WS_BLOCKS, 256>>>(X, ln_w, ln_b, spline_w, base_w,
                                                grid_rbf, grid_bs);
    fat_kernel<<<FAT_BLOCKS, 256>>>(out, base_w, scale, trans);
}